// round 1
// baseline (speedup 1.0000x reference)
#include <cuda_runtime.h>

#define B_  16
#define N_  16384
#define M_  256
#define TPB 256

// -------- scratch (device globals; no allocations allowed) --------
__device__ int   g_ind[B_ * N_];
__device__ float g_cnt[B_ * M_];
__device__ float g_sum[B_ * 3 * M_];
__device__ float g_gv[B_ * M_];
__device__ float g_sl1;

// -------- zero scratch (graph replays must be idempotent) --------
__global__ void k_zero() {
    int i = blockIdx.x * blockDim.x + threadIdx.x;
    if (i < B_ * M_) { g_cnt[i] = 0.f; g_gv[i] = 0.f; }
    if (i < B_ * 3 * M_) g_sum[i] = 0.f;
    if (i == 0) g_sl1 = 0.f;
}

// -------- kernel 1: argmin cdist + gt_offset + smooth-L1 + segment counts/sums --------
__global__ __launch_bounds__(TPB) void k_main(
    const float* __restrict__ data, const float* __restrict__ cp,
    const float* __restrict__ off,  const int* __restrict__ tc,
    const int* __restrict__ lab,    float* __restrict__ out)
{
    __shared__ float scx[M_], scy[M_], scz[M_], scn[M_];
    __shared__ float s_cnt[M_], s_sx[M_], s_sy[M_], s_sz[M_];
    __shared__ float s_red[TPB / 32];

    const int b = blockIdx.y;
    const int t = threadIdx.x;
    const int n = blockIdx.x * TPB + t;
    const int T = tc[b];

    // load contact points (TPB == M_: one element per thread)
    {
        float cx = cp[(b * M_ + t) * 3 + 0];
        float cy = cp[(b * M_ + t) * 3 + 1];
        float cz = cp[(b * M_ + t) * 3 + 2];
        scx[t] = cx; scy[t] = cy; scz[t] = cz;
        scn[t] = (cx * cx + cy * cy) + cz * cz;   // ||c||^2, ref op order
        s_cnt[t] = 0.f; s_sx[t] = 0.f; s_sy[t] = 0.f; s_sz[t] = 0.f;
    }
    __syncthreads();

    const float* dB = data + (size_t)b * 3 * N_;
    const float* oB = off  + (size_t)b * 3 * N_;
    float px = dB[n], py = dB[N_ + n], pz = dB[2 * N_ + n];
    float pn = (px * px + py * py) + pz * pz;     // ||p||^2, ref op order

    // argmin over valid contacts; replicate reference rounding exactly:
    // d2 = (||p||^2 + ||c||^2) - 2 * dot(p, c), dot as fma chain k=0,1,2
    int   bi = 0;
    float bd = __int_as_float(0x7f800000);        // +inf
    #pragma unroll 4
    for (int m = 0; m < T; m++) {
        float dot = fmaf(pz, scz[m], fmaf(py, scy[m], px * scx[m]));
        float d   = (pn + scn[m]) - 2.0f * dot;
        if (d < bd) { bd = d; bi = m; }           // strict < -> first-index argmin
    }

    const bool has = (T > 0);
    float gx = 0.f, gy = 0.f, gz = 0.f;
    if (has) { gx = scx[bi] - px; gy = scy[bi] - py; gz = scz[bi] - pz; }

    float* outB = out + (size_t)b * 3 * N_;
    outB[n] = gx; outB[N_ + n] = gy; outB[2 * N_ + n] = gz;
    g_ind[b * N_ + n] = has ? bi : 0;

    float ox = oB[n], oy = oB[N_ + n], oz = oB[2 * N_ + n];

    // smooth L1 partial (only batches with label == 1 contribute)
    float ls = 0.f;
    if (lab[b] == 1) {
        float d0 = gx - ox, d1 = gy - oy, d2 = gz - oz;
        float a0 = fabsf(d0), a1 = fabsf(d1), a2 = fabsf(d2);
        ls  = (a0 < 1.f) ? 0.5f * d0 * d0 : a0 - 0.5f;
        ls += (a1 < 1.f) ? 0.5f * d1 * d1 : a1 - 0.5f;
        ls += (a2 < 1.f) ? 0.5f * d2 * d2 : a2 - 0.5f;
    }
    // warp + block reduce -> one global atomic per block
    #pragma unroll
    for (int o = 16; o > 0; o >>= 1) ls += __shfl_down_sync(0xffffffffu, ls, o);
    if ((t & 31) == 0) s_red[t >> 5] = ls;
    __syncthreads();
    if (t == 0) {
        float s = 0.f;
        #pragma unroll
        for (int w = 0; w < TPB / 32; w++) s += s_red[w];
        if (s != 0.f) atomicAdd(&g_sl1, s);
    }

    // segment counts/sums of end points (SMEM aggregate, then flush)
    if (has) {  // uniform per block (depends only on b)
        float ex = px + ox, ey = py + oy, ez = pz + oz;
        atomicAdd(&s_cnt[bi], 1.f);
        atomicAdd(&s_sx[bi], ex);
        atomicAdd(&s_sy[bi], ey);
        atomicAdd(&s_sz[bi], ez);
        __syncthreads();
        float c = s_cnt[t];
        if (c != 0.f) {
            atomicAdd(&g_cnt[b * M_ + t], c);
            atomicAdd(&g_sum[(b * 3 + 0) * M_ + t], s_sx[t]);
            atomicAdd(&g_sum[(b * 3 + 1) * M_ + t], s_sy[t]);
            atomicAdd(&g_sum[(b * 3 + 2) * M_ + t], s_sz[t]);
        }
    }
}

// -------- kernel 2: per-cluster variance accumulation --------
__global__ __launch_bounds__(TPB) void k_var(
    const float* __restrict__ data, const float* __restrict__ off,
    const int* __restrict__ tc)
{
    const int b = blockIdx.y;
    const int T = tc[b];
    if (T == 0) return;  // excluded by where(has, ...)

    __shared__ float mx[M_], my[M_], mz[M_], sgv[M_];
    const int t = threadIdx.x;
    {
        float c   = fmaxf(g_cnt[b * M_ + t], 1.0f);
        mx[t] = g_sum[(b * 3 + 0) * M_ + t] / c;
        my[t] = g_sum[(b * 3 + 1) * M_ + t] / c;
        mz[t] = g_sum[(b * 3 + 2) * M_ + t] / c;
        sgv[t] = 0.f;
    }
    __syncthreads();

    const int n = blockIdx.x * TPB + t;
    const float* dB = data + (size_t)b * 3 * N_;
    const float* oB = off  + (size_t)b * 3 * N_;
    float ex = dB[n]          + oB[n];
    float ey = dB[N_ + n]     + oB[N_ + n];
    float ez = dB[2 * N_ + n] + oB[2 * N_ + n];

    int mi = g_ind[b * N_ + n];
    float dx = ex - mx[mi], dy = ey - my[mi], dz = ez - mz[mi];
    float v = (dx * dx + dy * dy) + dz * dz;

    atomicAdd(&sgv[mi], v);
    __syncthreads();
    if (sgv[t] != 0.f) atomicAdd(&g_gv[b * M_ + t], sgv[t]);
}

// -------- kernel 3: finalize losses, write scalar --------
__global__ __launch_bounds__(TPB) void k_final(
    const int* __restrict__ tc, const int* __restrict__ lab,
    float* __restrict__ out)
{
    __shared__ float s_red[TPB / 32];
    const int t = threadIdx.x;

    float acc = 0.f;
    for (int idx = t; idx < B_ * M_; idx += TPB) {
        int b = idx / M_;
        if (tc[b] > 0) {
            float c = g_cnt[idx];
            if (c > 0.f) acc += g_gv[idx] / fmaxf(c, 1.0f);
        }
    }
    #pragma unroll
    for (int o = 16; o > 0; o >>= 1) acc += __shfl_down_sync(0xffffffffu, acc, o);
    if ((t & 31) == 0) s_red[t >> 5] = acc;
    __syncthreads();

    if (t == 0) {
        float vs = 0.f;
        #pragma unroll
        for (int w = 0; w < TPB / 32; w++) vs += s_red[w];
        float nvalid = 0.f, nsel = 0.f;
        for (int b = 0; b < B_; b++) {
            if (tc[b] > 0)   nvalid += 1.f;
            if (lab[b] == 1) nsel   += 1.f;
        }
        nsel *= 3.0f * (float)N_;
        float offset_loss = (nsel > 0.f) ? g_sl1 / fmaxf(nsel, 1.0f) : 0.f;
        float var_loss    = vs / (nvalid + 1e-16f);
        out[(size_t)B_ * 3 * N_] = offset_loss * 10.0f + var_loss * 2.0f;
    }
}

extern "C" void kernel_launch(void* const* d_in, const int* in_sizes, int n_in,
                              void* d_out, int out_size) {
    const float* data = (const float*)d_in[0];
    const float* cp   = (const float*)d_in[1];
    const float* off  = (const float*)d_in[2];
    const int*   tc   = (const int*)d_in[3];
    const int*   lab  = (const int*)d_in[4];
    float* out = (float*)d_out;

    k_zero<<<(B_ * 3 * M_ + TPB - 1) / TPB, TPB>>>();
    dim3 grid(N_ / TPB, B_);
    k_main<<<grid, TPB>>>(data, cp, off, tc, lab, out);
    k_var<<<grid, TPB>>>(data, off, tc);
    k_final<<<1, TPB>>>(tc, lab, out);
}

// round 2
// speedup vs baseline: 1.0571x; 1.0571x over previous
#include <cuda_runtime.h>

#define B_  16
#define N_  16384
#define M_  256
#define TPB 256
#define PPT 2          // points per thread in k_main

// -------- scratch (device globals; zero-initialized at module load;
//          k_final re-zeroes at end of every launch -> graph-idempotent) ----
__device__ float g_cnt[B_ * M_];
__device__ float g_sum[3 * B_ * M_];   // plane-major: [k][b][m]
__device__ float g_sq [B_ * M_];
__device__ float g_sl1;

// ===== kernel 1: argmin cdist + gt_offset + smooth-L1 + segment stats =====
__global__ __launch_bounds__(TPB) void k_main(
    const float* __restrict__ data, const float* __restrict__ cp,
    const float* __restrict__ off,  const int* __restrict__ tc,
    const int* __restrict__ lab,    float* __restrict__ out)
{
    __shared__ float4 sc[M_];                         // {cx,cy,cz,||c||^2}
    __shared__ float s_cnt[M_], s_sx[M_], s_sy[M_], s_sz[M_], s_sq[M_];
    __shared__ float s_red[TPB / 32];

    const int b = blockIdx.y;
    const int t = threadIdx.x;
    const int T = tc[b];

    {   // TPB == M_: one contact per thread
        float cx = cp[(b * M_ + t) * 3 + 0];
        float cy = cp[(b * M_ + t) * 3 + 1];
        float cz = cp[(b * M_ + t) * 3 + 2];
        sc[t] = make_float4(cx, cy, cz, (cx * cx + cy * cy) + cz * cz);
        s_cnt[t] = 0.f; s_sx[t] = 0.f; s_sy[t] = 0.f; s_sz[t] = 0.f; s_sq[t] = 0.f;
    }
    __syncthreads();

    const int n0 = blockIdx.x * (TPB * PPT) + t;
    const int n1 = n0 + TPB;
    const float* dB = data + (size_t)b * 3 * N_;
    const float* oB = off  + (size_t)b * 3 * N_;

    float px0 = dB[n0], py0 = dB[N_ + n0], pz0 = dB[2 * N_ + n0];
    float px1 = dB[n1], py1 = dB[N_ + n1], pz1 = dB[2 * N_ + n1];
    float pn0 = (px0 * px0 + py0 * py0) + pz0 * pz0;   // ref op order
    float pn1 = (px1 * px1 + py1 * py1) + pz1 * pz1;

    // argmin; replicate reference fp exactly:
    // d2 = (||p||^2 + ||c||^2) - 2*dot, dot = fma chain, strict '<'
    int   bi0 = 0, bi1 = 0;
    float bd0 = __int_as_float(0x7f800000);
    float bd1 = bd0;
    #pragma unroll 4
    for (int m = 0; m < T; m++) {
        float4 c = sc[m];                               // LDS.128 broadcast
        float dot0 = fmaf(pz0, c.z, fmaf(py0, c.y, px0 * c.x));
        float d0   = (pn0 + c.w) - 2.0f * dot0;
        if (d0 < bd0) { bd0 = d0; bi0 = m; }
        float dot1 = fmaf(pz1, c.z, fmaf(py1, c.y, px1 * c.x));
        float d1   = (pn1 + c.w) - 2.0f * dot1;
        if (d1 < bd1) { bd1 = d1; bi1 = m; }
    }

    const bool has = (T > 0);
    float gx0 = 0.f, gy0 = 0.f, gz0 = 0.f, gx1 = 0.f, gy1 = 0.f, gz1 = 0.f;
    if (has) {
        float4 c0 = sc[bi0], c1 = sc[bi1];
        gx0 = c0.x - px0; gy0 = c0.y - py0; gz0 = c0.z - pz0;
        gx1 = c1.x - px1; gy1 = c1.y - py1; gz1 = c1.z - pz1;
    }

    float* outB = out + (size_t)b * 3 * N_;
    outB[n0] = gx0; outB[N_ + n0] = gy0; outB[2 * N_ + n0] = gz0;
    outB[n1] = gx1; outB[N_ + n1] = gy1; outB[2 * N_ + n1] = gz1;

    float ox0 = oB[n0], oy0 = oB[N_ + n0], oz0 = oB[2 * N_ + n0];
    float ox1 = oB[n1], oy1 = oB[N_ + n1], oz1 = oB[2 * N_ + n1];

    // smooth L1 (only label==1 batches contribute)
    float ls = 0.f;
    if (lab[b] == 1) {
        float d, a;
        d = gx0 - ox0; a = fabsf(d); ls += (a < 1.f) ? 0.5f * d * d : a - 0.5f;
        d = gy0 - oy0; a = fabsf(d); ls += (a < 1.f) ? 0.5f * d * d : a - 0.5f;
        d = gz0 - oz0; a = fabsf(d); ls += (a < 1.f) ? 0.5f * d * d : a - 0.5f;
        d = gx1 - ox1; a = fabsf(d); ls += (a < 1.f) ? 0.5f * d * d : a - 0.5f;
        d = gy1 - oy1; a = fabsf(d); ls += (a < 1.f) ? 0.5f * d * d : a - 0.5f;
        d = gz1 - oz1; a = fabsf(d); ls += (a < 1.f) ? 0.5f * d * d : a - 0.5f;
    }
    #pragma unroll
    for (int o = 16; o > 0; o >>= 1) ls += __shfl_down_sync(0xffffffffu, ls, o);
    if ((t & 31) == 0) s_red[t >> 5] = ls;
    __syncthreads();
    if (t == 0) {
        float s = 0.f;
        #pragma unroll
        for (int w = 0; w < TPB / 32; w++) s += s_red[w];
        if (s != 0.f) atomicAdd(&g_sl1, s);
    }

    // segment counts / sums / sum-of-squares of end points e = p + off
    if (has) {   // uniform per block
        float ex0 = px0 + ox0, ey0 = py0 + oy0, ez0 = pz0 + oz0;
        float ex1 = px1 + ox1, ey1 = py1 + oy1, ez1 = pz1 + oz1;
        atomicAdd(&s_cnt[bi0], 1.f);
        atomicAdd(&s_sx[bi0], ex0); atomicAdd(&s_sy[bi0], ey0); atomicAdd(&s_sz[bi0], ez0);
        atomicAdd(&s_sq[bi0], (ex0 * ex0 + ey0 * ey0) + ez0 * ez0);
        atomicAdd(&s_cnt[bi1], 1.f);
        atomicAdd(&s_sx[bi1], ex1); atomicAdd(&s_sy[bi1], ey1); atomicAdd(&s_sz[bi1], ez1);
        atomicAdd(&s_sq[bi1], (ex1 * ex1 + ey1 * ey1) + ez1 * ez1);
        __syncthreads();
        float c = s_cnt[t];
        if (c != 0.f) {
            int idx = b * M_ + t;
            atomicAdd(&g_cnt[idx], c);
            atomicAdd(&g_sum[0 * B_ * M_ + idx], s_sx[t]);
            atomicAdd(&g_sum[1 * B_ * M_ + idx], s_sy[t]);
            atomicAdd(&g_sum[2 * B_ * M_ + idx], s_sz[t]);
            atomicAdd(&g_sq[idx], s_sq[t]);
        }
    }
}

// ===== kernel 2: finalize losses (variance identity) + re-zero scratch =====
__global__ __launch_bounds__(TPB) void k_final(
    const int* __restrict__ tc, const int* __restrict__ lab,
    float* __restrict__ out)
{
    __shared__ int   s_tc[B_];
    __shared__ float s_red[TPB / 32];
    const int t = threadIdx.x;

    if (t < B_) s_tc[t] = tc[t];
    __syncthreads();

    // per-cluster: gmean = (sum||e||^2 - ||sum e||^2 / c) / c ; sum where c>0
    float acc = 0.f;
    #pragma unroll
    for (int idx = t; idx < B_ * M_; idx += TPB) {
        int b = idx >> 8;                          // M_ == 256
        float c = g_cnt[idx];
        if (s_tc[b] > 0 && c > 0.f) {
            float sx = g_sum[0 * B_ * M_ + idx];
            float sy = g_sum[1 * B_ * M_ + idx];
            float sz = g_sum[2 * B_ * M_ + idx];
            float vs = g_sq[idx] - ((sx * sx + sy * sy) + sz * sz) / c;
            acc += vs / c;
        }
    }
    #pragma unroll
    for (int o = 16; o > 0; o >>= 1) acc += __shfl_down_sync(0xffffffffu, acc, o);
    if ((t & 31) == 0) s_red[t >> 5] = acc;

    // nvalid / nsel via ballot in warp 0 (no serial loads)
    float nvalid = 0.f, nsel = 0.f;
    if (t < 32) {
        int v = (t < B_) ? s_tc[t] : 0;
        int l = (t < B_) ? lab[t] : 0;
        unsigned mv = __ballot_sync(0xffffffffu, v > 0);
        unsigned ml = __ballot_sync(0xffffffffu, l == 1);
        nvalid = (float)__popc(mv);
        nsel   = (float)__popc(ml);
    }
    __syncthreads();

    if (t == 0) {
        float vs = 0.f;
        #pragma unroll
        for (int w = 0; w < TPB / 32; w++) vs += s_red[w];
        nsel *= 3.0f * (float)N_;
        float offset_loss = (nsel > 0.f) ? g_sl1 / fmaxf(nsel, 1.0f) : 0.f;
        float var_loss    = vs / (nvalid + 1e-16f);
        out[(size_t)B_ * 3 * N_] = offset_loss * 10.0f + var_loss * 2.0f;
    }

    // re-zero scratch for the next graph replay
    __syncthreads();
    #pragma unroll
    for (int idx = t; idx < B_ * M_; idx += TPB) {
        g_cnt[idx] = 0.f; g_sq[idx] = 0.f;
        g_sum[0 * B_ * M_ + idx] = 0.f;
        g_sum[1 * B_ * M_ + idx] = 0.f;
        g_sum[2 * B_ * M_ + idx] = 0.f;
    }
    if (t == 0) g_sl1 = 0.f;
}

extern "C" void kernel_launch(void* const* d_in, const int* in_sizes, int n_in,
                              void* d_out, int out_size) {
    const float* data = (const float*)d_in[0];
    const float* cp   = (const float*)d_in[1];
    const float* off  = (const float*)d_in[2];
    const int*   tc   = (const int*)d_in[3];
    const int*   lab  = (const int*)d_in[4];
    float* out = (float*)d_out;

    dim3 grid(N_ / (TPB * PPT), B_);
    k_main<<<grid, TPB>>>(data, cp, off, tc, lab, out);
    k_final<<<1, TPB>>>(tc, lab, out);
}